// round 3
// baseline (speedup 1.0000x reference)
#include <cuda_runtime.h>

#define NB 4
#define NC 19
#define NH 192
#define NW 192
#define HW (NH*NW)
#define THETA 40.0f
#define PAD 193
#define SMEM_BYTES (NH*PAD*4)
#define CHK 8
#define NCHK (NH/CHK)   // 24

// Scratch (device globals: no runtime allocation allowed)
__device__ float g_colagg[NB*NC*HW];   // per-(b,c) column aggregation (final values)
__device__ float g_D   [NB*HW];        // D[b][i][j]  = exp(-theta * relu(edge))
__device__ float g_Dt  [NB*HW];        // Dt[b][j][i] = D[b][i][j]
__device__ float g_Zc  [NB*HW];        // column ones-scan result
__device__ float g_ST  [NB*HW];        // row ones-scan forward scratch (transposed)
__device__ float g_Zinv[NB*HW];        // 1/Z

// ---------------------------------------------------------------------------
// PK1: per (b,j) column: compute decays D, Dt, and column ones-scan Zc.
// Zc[i] = S_i + T_i - 1 with f==1.
// ---------------------------------------------------------------------------
__global__ void pk1_kernel(const float* __restrict__ edge) {
    int t = blockIdx.x * blockDim.x + threadIdx.x;   // 0 .. NB*NW-1
    if (t >= NB*NW) return;
    int b = t / NW;
    int j = t - b*NW;
    const float* eb = edge + b*HW + j;     // stride NW over i
    float* Db  = g_D  + b*HW + j;          // stride NW over i
    float* Zb  = g_Zc + b*HW + j;          // stride NW over i
    float* Dtb = g_Dt + b*HW + j*NW;       // Dt[b][j][i], stride 1 over i

    float S = 0.f;
    #pragma unroll 4
    for (int i = 0; i < NH; ++i) {
        float e = fmaxf(eb[i*NW], 0.f);
        float d = __expf(-THETA * e);
        Db[i*NW] = d;
        Dtb[i]   = d;
        S = d * S + 1.f;                   // S_0 = 1 (d_0 multiplies 0)
        Zb[i*NW] = S;
    }
    float T = 0.f, c = 0.f;                // T_i = 1 + d_{i+1} T_{i+1}, T_{H-1}=1
    #pragma unroll 4
    for (int i = NH-1; i >= 0; --i) {
        T = 1.f + c * T;
        Zb[i*NW] += T - 1.f;               // Zc = S + T - 1
        c = Db[i*NW];
    }
}

// ---------------------------------------------------------------------------
// PK2: per (b,i) row: row ones-scan (decays read coalesced via Dt),
// combine with Zc, write Zinv = 1/(Zc + Zr), Zr = Sr + Tr - 2.
// ---------------------------------------------------------------------------
__global__ void pk2_kernel() {
    int t = blockIdx.x * blockDim.x + threadIdx.x;   // 0 .. NB*NH-1
    if (t >= NB*NH) return;
    int b = t / NH;
    int i = t - b*NH;
    const float* Dti = g_Dt + b*HW + i;    // Dt[b][j][i], stride NW over j (coalesced over threads)
    float* STb = g_ST + b*HW + i;          // same transposed layout
    const float* Zcb = g_Zc   + b*HW + i*NW;
    float* Zib       = g_Zinv + b*HW + i*NW;

    float S = 0.f;
    #pragma unroll 4
    for (int j = 0; j < NW; ++j) {
        float d = Dti[j*NW];
        S = d * S + 1.f;
        STb[j*NW] = S;
    }
    float T = 0.f, c = 0.f;
    #pragma unroll 4
    for (int j = NW-1; j >= 0; --j) {
        T = 1.f + c * T;
        float Zr = STb[j*NW] + T - 2.f;    // exclude s==j
        float Zc = Zcb[j];                 // uncoalesced, tiny + L2-hot
        Zib[j] = 1.f / (Zc + Zr);
        c = Dti[j*NW];
    }
}

// ---------------------------------------------------------------------------
// Iteration kernel: one CTA per (b,c) slice. Slice lives in smem A[192][193]
// (pad 193 => conflict-free for both per-column and per-row thread access).
//   Phase A: col scans (thread per column j). Forward pass keeps only every-
//            CHKth prefix S in registers; backward pass recomputes in-block S
//            (smem/L1-hot) and writes FINAL colagg = S + T - f to global ONCE.
//   Phase B: row scans in-place in smem (thread per row i): forward overwrites
//            with S, backward recovers f_j = S_j - d_j*S_{j-1} and writes
//            rowagg = S + T - 2f.
//   Phase C: out = (colagg + rowagg) * Zinv   (all coalesced).
// In-place fin==fout is safe: each CTA fully reads its slice in the load phase
// before writing in phase C.
// ---------------------------------------------------------------------------
__global__ void __launch_bounds__(256, 1)
iter_kernel(const float* __restrict__ fin, float* __restrict__ fout) {
    extern __shared__ float A[];           // [NH][PAD]
    int bc = blockIdx.x;                   // b*NC + c
    int b  = bc / NC;
    int base  = bc * HW;
    int dbase = b  * HW;
    int tid = threadIdx.x;

    // load slice (coalesced)
    for (int idx = tid; idx < HW; idx += 256) {
        int i = idx / NW;
        int j = idx - i*NW;
        A[i*PAD + j] = fin[base + idx];
    }
    __syncthreads();

    // Phase A: column scans, thread per column j (checkpoint + recompute)
    if (tid < NW) {
        int j = tid;
        const float* Dj = g_D + dbase + j;       // stride NW over i (L1-hot, shared by 19 channels)
        float* cg = g_colagg + base + j;         // stride NW over i (coalesced)

        float chk[NCHK];
        float S = 0.f;
        #pragma unroll
        for (int bi = 0; bi < NCHK; ++bi) {
            #pragma unroll
            for (int k = 0; k < CHK; ++k) {
                int i = bi*CHK + k;
                S = Dj[i*NW] * S + A[i*PAD + j];
            }
            chk[bi] = S;
        }
        float T = 0.f, c = 0.f;                  // c = d_{i+1}
        #pragma unroll
        for (int bi = NCHK-1; bi >= 0; --bi) {
            float s = (bi > 0) ? chk[bi-1] : 0.f;
            float sl[CHK], fl[CHK], dl[CHK];
            #pragma unroll
            for (int k = 0; k < CHK; ++k) {      // recompute (non-chained across blocks)
                int i = bi*CHK + k;
                fl[k] = A[i*PAD + j];
                dl[k] = Dj[i*NW];
                s = dl[k] * s + fl[k];
                sl[k] = s;
            }
            #pragma unroll
            for (int k = CHK-1; k >= 0; --k) {
                int i = bi*CHK + k;
                T = fl[k] + c * T;               // T_{H-1} = f
                cg[i*NW] = sl[k] + T - fl[k];    // colagg = S + T - f (single write)
                c = dl[k];
            }
        }
    }
    __syncthreads();                             // col threads done with A reads

    // Phase B: row scans in-place, thread per row i
    if (tid < NH) {
        int i = tid;
        const float* Dti = g_Dt + dbase + i;     // Dt[b][j][i], stride NW over j
        float* Ai = A + i*PAD;
        float S = 0.f;
        #pragma unroll 4
        for (int j = 0; j < NW; ++j) {
            float d = Dti[j*NW];
            S = d * S + Ai[j];
            Ai[j] = S;                           // A now holds S_j
        }
        float T = 0.f, c = 0.f;
        #pragma unroll 4
        for (int j = NW-1; j >= 0; --j) {
            float Sj = Ai[j];
            float dj = (j > 0) ? Dti[j*NW] : 0.f;
            float f  = (j > 0) ? (Sj - dj * Ai[j-1]) : Sj;   // recover f from S
            T = f + c * T;                       // T_{W-1} = f
            Ai[j] = Sj + T - 2.f*f;              // rowagg (excludes s==j)
            c = dj;
        }
    }
    __syncthreads();

    // Phase C: combine (coalesced)
    const float* __restrict__ Zi = g_Zinv + dbase;
    const float* __restrict__ cg = g_colagg + base;
    for (int idx = tid; idx < HW; idx += 256) {
        int i = idx / NW;
        int j = idx - i*NW;
        fout[base + idx] = (cg[idx] + A[i*PAD + j]) * Zi[idx];
    }
}

// ---------------------------------------------------------------------------
extern "C" void kernel_launch(void* const* d_in, const int* in_sizes, int n_in,
                              void* d_out, int out_size) {
    const float* mask = (const float*)d_in[0];   // (4,19,192,192) fp32
    const float* edge = (const float*)d_in[1];   // (4,1,192,192)  fp32
    // d_in[2] = iter (3, fixed by the dataset; graph structure must be static)
    float* out = (float*)d_out;

    cudaFuncSetAttribute(iter_kernel,
                         cudaFuncAttributeMaxDynamicSharedMemorySize, SMEM_BYTES);

    pk1_kernel<<<24, 32>>>(edge);                // 768 threads: per-(b,j) columns
    pk2_kernel<<<24, 32>>>();                    // 768 threads: per-(b,i) rows

    iter_kernel<<<NB*NC, 256, SMEM_BYTES>>>(mask, out);  // iter 1
    iter_kernel<<<NB*NC, 256, SMEM_BYTES>>>(out,  out);  // iter 2 (in-place safe)
    iter_kernel<<<NB*NC, 256, SMEM_BYTES>>>(out,  out);  // iter 3
}